// round 11
// baseline (speedup 1.0000x reference)
#include <cuda_runtime.h>
#include <cstdint>

#define KK 24
#define TT 512
#define BATCH 2048

// fused final-reduction state (self-resetting -> deterministic across replays)
__device__ double g_sum;
__device__ unsigned int g_ticket;

typedef unsigned long long u64;

// ---- packed f32x2 helpers ----
static __device__ __forceinline__ u64 fma2(u64 a, u64 b, u64 c) {
    u64 d;
    asm("fma.rn.f32x2 %0, %1, %2, %3;" : "=l"(d) : "l"(a), "l"(b), "l"(c));
    return d;
}
static __device__ __forceinline__ u64 mul2(u64 a, u64 b) {
    u64 d;
    asm("mul.rn.f32x2 %0, %1, %2;" : "=l"(d) : "l"(a), "l"(b));
    return d;
}
static __device__ __forceinline__ u64 add2(u64 a, u64 b) {
    u64 d;
    asm("add.rn.f32x2 %0, %1, %2;" : "=l"(d) : "l"(a), "l"(b));
    return d;
}
static __device__ __forceinline__ void upk(u64 v, float& lo, float& hi) {
    asm("mov.b64 {%0, %1}, %2;" : "=f"(lo), "=f"(hi) : "l"(v));
}
static __device__ __forceinline__ u64 pk(float lo, float hi) {
    u64 r;
    asm("mov.b64 %0, {%1, %2};" : "=l"(r) : "f"(lo), "f"(hi));
    return r;
}
static __device__ __forceinline__ float pmax(u64 v) {
    float lo, hi;
    upk(v, lo, hi);
    return fmaxf(lo, hi);
}

// one recursion step for ONE batch; v is 24 floats in shared (u64-pair view).
// f32x2 packs STATE pairs: E2[k] = (e_{2k}, e_{2k+1}) matching v pairs.
template <bool RN>
static __device__ __forceinline__ void step1(const u64* __restrict__ src,
                                             float* __restrict__ dst, int lane,
                                             const u64* __restrict__ E2,
                                             float fe, float& s) {
    const ulonglong2* vp = reinterpret_cast<const ulonglong2*>(src);
    ulonglong2 q0 = vp[0], q1 = vp[1], q2 = vp[2];
    ulonglong2 q3 = vp[3], q4 = vp[4], q5 = vp[5];

    // 4 parallel chains of depth 3 over state-pairs
    u64 c0 = mul2(E2[0], q0.x);
    u64 c1 = mul2(E2[1], q0.y);
    u64 c2 = mul2(E2[2], q1.x);
    u64 c3 = mul2(E2[3], q1.y);
    c0 = fma2(E2[4], q2.x, c0);
    c1 = fma2(E2[5], q2.y, c1);
    c2 = fma2(E2[6], q3.x, c2);
    c3 = fma2(E2[7], q3.y, c3);
    c0 = fma2(E2[8], q4.x, c0);
    c1 = fma2(E2[9], q4.y, c1);
    c2 = fma2(E2[10], q5.x, c2);
    c3 = fma2(E2[11], q5.y, c3);
    u64 ct = add2(add2(c0, c1), add2(c2, c3));
    float d0, d1;
    upk(ct, d0, d1);
    float vnew;
    if (RN) {
        // renorm by max of previous vector (lane-uniform, register-only)
        float m = fmaxf(fmaxf(pmax(q0.x), pmax(q0.y)), fmaxf(pmax(q1.x), pmax(q1.y)));
        m = fmaxf(m, fmaxf(fmaxf(pmax(q2.x), pmax(q2.y)), fmaxf(pmax(q3.x), pmax(q3.y))));
        m = fmaxf(m, fmaxf(fmaxf(pmax(q4.x), pmax(q4.y)), fmaxf(pmax(q5.x), pmax(q5.y))));
        vnew = (d0 + d1) * fe * (1.0f / m);
        s += __logf(m);
    } else {
        vnew = (d0 + d1) * fe;
    }
    dst[lane] = vnew;
}

#define STEP(S, D, RN, IDX)                                                        \
    do {                                                                           \
        step1<RN>((const u64*)&vs[w][S][0], &vs[w][D][0], lane, E2, fe[IDX], s);   \
        __syncwarp();                                                              \
    } while (0)

#define WIN8(RN0)            \
    STEP(0, 1, RN0, 0);      \
    STEP(1, 0, false, 1);    \
    STEP(0, 1, false, 2);    \
    STEP(1, 0, false, 3);    \
    STEP(0, 1, false, 4);    \
    STEP(1, 0, false, 5);    \
    STEP(0, 1, false, 6);    \
    STEP(1, 0, false, 7)

__global__ __launch_bounds__(64, 14) void crf_kernel(const float* __restrict__ feats,
                                                     const float* __restrict__ trans,
                                                     const void* __restrict__ tags,
                                                     const int* __restrict__ startp,
                                                     float* __restrict__ out) {
    __shared__ __align__(16) float vs[2][2][32];  // [warp][buf][lane]
    __shared__ float sc_sh;    // backward warp's scale sum
    __shared__ float gold_sh;  // backward warp's gold partial
    const int lane = threadIdx.x & 31;
    const int w = threadIdx.x >> 5;  // 0 = forward, 1 = backward
    const int b = blockIdx.x;
    const int j = (lane < KK) ? lane : (KK - 1);

    const int start = startp[0];  // low word valid for LE int32/int64

    // E2: forward = row j of exp(trans) paired over i; backward = column j (E^T)
    u64 E2[12];
    if (w == 0) {
#pragma unroll
        for (int k = 0; k < 12; ++k)
            E2[k] = pk(__expf(trans[j * KK + 2 * k]), __expf(trans[j * KK + 2 * k + 1]));
    } else {
#pragma unroll
        for (int k = 0; k < 12; ++k)
            E2[k] = pk(__expf(trans[(2 * k) * KK + j]), __expf(trans[(2 * k + 1) * KK + j]));
    }

    float s = 0.0f;
    const float* fb = feats + b * (TT * KK) + j;
    float fn[8], fe[8];

    if (w == 0) {
        // ---------------- forward: alpha, t = 1..256 (32 windows of 8) ----------------
        vs[0][0][lane] = (lane == start) ? 1.0f : 0.0f;
#pragma unroll
        for (int r = 0; r < 8; ++r) fn[r] = __ldg(fb + (1 + r) * KK);
        __syncwarp();
        {
#pragma unroll
            for (int r = 0; r < 8; ++r) fe[r] = __expf(fn[r]);
            const float* p = fb + 9 * KK;
#pragma unroll
            for (int r = 0; r < 8; ++r) fn[r] = __ldg(p + r * KK);
            WIN8(false);
        }
#pragma unroll 1
        for (int wi = 1; wi < 32; ++wi) {
#pragma unroll
            for (int r = 0; r < 8; ++r) fe[r] = __expf(fn[r]);
            const float* p = fb + (8 * (wi + 1) + 1) * KK;  // max base 257: in-bounds
#pragma unroll
            for (int r = 0; r < 8; ++r) fn[r] = __ldg(p + r * KK);
            WIN8(true);
        }
        // alpha(256) in vs[0][0]
    } else {
        // -------- backward: s(t)=fe_t*beta(t), t = 511..257, then beta(256) ----------
#pragma unroll
        for (int r = 0; r < 7; ++r) fn[r] = __ldg(fb + (511 - r) * KK);
#pragma unroll
        for (int r = 0; r < 7; ++r) fe[r] = __expf(fn[r]);
        vs[1][0][lane] = (lane < KK) ? fe[0] : 0.0f;  // s(511)
#pragma unroll
        for (int r = 0; r < 8; ++r) fn[r] = __ldg(fb + (504 - r) * KK);
        __syncwarp();
        // prologue: t = 510..505
        STEP(0, 1, false, 1);
        STEP(1, 0, false, 2);
        STEP(0, 1, false, 3);
        STEP(1, 0, false, 4);
        STEP(0, 1, false, 5);
        STEP(1, 0, false, 6);
        // 31 windows of 8: t = 504..257
#pragma unroll 1
        for (int wi = 0; wi < 31; ++wi) {
#pragma unroll
            for (int r = 0; r < 8; ++r) fe[r] = __expf(fn[r]);
            const float* p = fb + (504 - 8 * (wi + 1)) * KK;  // min base 256: in-bounds
#pragma unroll
            for (int r = 0; r < 8; ++r) fn[r] = __ldg(p + r * KK);
            WIN8(true);
        }
        // final fe-free step: beta(256) = E^T s(257)
        step1<false>((const u64*)&vs[1][0][0], &vs[1][1][0], lane, E2, 1.0f, s);
        __syncwarp();
        if (lane == 0) sc_sh = s;
        // beta(256) in vs[1][1]
    }

    // ---- gold score: warps split the t-range of batch b ----
    const unsigned int* wds = (const unsigned int*)tags;
    unsigned int hiw = wds[2 * lane + 1];
    const int is64 = (__ballot_sync(0xffffffffu, hiw != 0u) == 0u);
    float g = 0.0f;
    if (is64) {
        const long long* tg = (const long long*)tags + b * TT;
#pragma unroll
        for (int t = 1 + lane + 32 * w; t < TT; t += 64) {
            int it = (int)tg[t], ip = (int)tg[t - 1];
            g += trans[it * KK + ip] + __ldg(feats + (b * TT + t) * KK + it);
        }
    } else {
        const int* tg = (const int*)tags + b * TT;
#pragma unroll
        for (int t = 1 + lane + 32 * w; t < TT; t += 64) {
            int it = tg[t], ip = tg[t - 1];
            g += trans[it * KK + ip] + __ldg(feats + (b * TT + t) * KK + it);
        }
    }
#pragma unroll
    for (int o = 16; o > 0; o >>= 1) g += __shfl_xor_sync(0xffffffffu, g, o);
    if (w == 1 && lane == 0) gold_sh = g;

    __syncthreads();

    // ---- combine (forward warp): score = log(sum_j alpha_j * beta_j) + sF + sB ----
    if (w == 0) {
        float prod = (lane < KK) ? vs[0][0][lane] * vs[1][1][lane] : 0.0f;
#pragma unroll
        for (int o = 16; o > 0; o >>= 1) prod += __shfl_xor_sync(0xffffffffu, prod, o);
        float fwd = __logf(prod) + s + sc_sh;

        if (lane == 0) {
            double part = (double)fwd - (double)g - (double)gold_sh;
            atomicAdd(&g_sum, part);
            __threadfence();
            unsigned int old = atomicAdd(&g_ticket, 1u);
            if (old == (unsigned)(BATCH - 1)) {
                __threadfence();
                out[0] = (float)(g_sum * (1.0 / (double)BATCH));
                g_sum = 0.0;   // self-reset for next graph replay
                g_ticket = 0u;
            }
        }
    }
}

extern "C" void kernel_launch(void* const* d_in, const int* in_sizes, int n_in,
                              void* d_out, int out_size) {
    const float* feats = (const float*)d_in[0];
    const float* trans = (const float*)d_in[1];
    const void* tags = d_in[2];
    const int* startp = (const int*)d_in[3];

    crf_kernel<<<BATCH, 64>>>(feats, trans, tags, startp, (float*)d_out);
}

// round 12
// speedup vs baseline: 1.1819x; 1.1819x over previous
#include <cuda_runtime.h>
#include <cstdint>

#define KK 24
#define TT 512
#define BATCH 2048

// fused final-reduction state (self-resetting -> deterministic across replays)
__device__ double g_sum;
__device__ unsigned int g_ticket;

typedef unsigned int u32;
typedef unsigned short u16;

// ---- bf16x2 helpers ----
static __device__ __forceinline__ u32 bffma2(u32 a, u32 b, u32 c) {
    u32 d;
    asm("fma.rn.bf16x2 %0, %1, %2, %3;" : "=r"(d) : "r"(a), "r"(b), "r"(c));
    return d;
}
static __device__ __forceinline__ u32 bfmul2(u32 a, u32 b) {
    u32 d;
    asm("mul.rn.bf16x2 %0, %1, %2;" : "=r"(d) : "r"(a), "r"(b));
    return d;
}
static __device__ __forceinline__ u32 bfadd2(u32 a, u32 b) {
    u32 d;
    asm("add.rn.bf16x2 %0, %1, %2;" : "=r"(d) : "r"(a), "r"(b));
    return d;
}
static __device__ __forceinline__ u32 bfmax2(u32 a, u32 b) {
    u32 d;
    asm("max.bf16x2 %0, %1, %2;" : "=r"(d) : "r"(a), "r"(b));
    return d;
}
// widen bf16x2 -> 2 floats
static __device__ __forceinline__ void bf2f(u32 v, float& lo, float& hi) {
    u16 l, h;
    asm("mov.b32 {%0, %1}, %2;" : "=h"(l), "=h"(h) : "r"(v));
    asm("cvt.f32.bf16 %0, %1;" : "=f"(lo) : "h"(l));
    asm("cvt.f32.bf16 %0, %1;" : "=f"(hi) : "h"(h));
}
static __device__ __forceinline__ u16 f2bf(float f) {
    u16 h;
    asm("cvt.rn.bf16.f32 %0, %1;" : "=h"(h) : "f"(f));
    return h;
}
// pack (lo, hi) floats -> bf16x2 (PTX: first src -> high half)
static __device__ __forceinline__ u32 pkbf(float lo, float hi) {
    u32 r;
    asm("cvt.rn.bf16x2.f32 %0, %1, %2;" : "=r"(r) : "f"(hi), "f"(lo));
    return r;
}

// one recursion step for ONE batch; v = 24 bf16 in shared.
// E2[k] = bf16x2 (E_{j,2k}, E_{j,2k+1}); q[k] = (v_{2k}, v_{2k+1}).
template <bool RN>
static __device__ __forceinline__ void step1(const u16* __restrict__ src,
                                             u16* __restrict__ dst, int lane,
                                             const u32* __restrict__ E2,
                                             float fe, float& s) {
    const uint4* vp = reinterpret_cast<const uint4*>(src);
    uint4 a = vp[0], b = vp[1], c = vp[2];  // 3 x LDS.128 = 24 bf16 (slots 0..23)
    u32 q0 = a.x, q1 = a.y, q2 = a.z, q3 = a.w;
    u32 q4 = b.x, q5 = b.y, q6 = b.z, q7 = b.w;
    u32 q8 = c.x, q9 = c.y, q10 = c.z, q11 = c.w;

    // 4 parallel chains of depth 3 over state-pairs (bf16 accumulate)
    u32 c0 = bfmul2(E2[0], q0);
    u32 c1 = bfmul2(E2[1], q1);
    u32 c2 = bfmul2(E2[2], q2);
    u32 c3 = bfmul2(E2[3], q3);
    c0 = bffma2(E2[4], q4, c0);
    c1 = bffma2(E2[5], q5, c1);
    c2 = bffma2(E2[6], q6, c2);
    c3 = bffma2(E2[7], q7, c3);
    c0 = bffma2(E2[8], q8, c0);
    c1 = bffma2(E2[9], q9, c1);
    c2 = bffma2(E2[10], q10, c2);
    c3 = bffma2(E2[11], q11, c3);
    u32 ct = bfadd2(bfadd2(c0, c1), bfadd2(c2, c3));
    float d0, d1;
    bf2f(ct, d0, d1);

    float vnew;
    if (RN) {
        // renorm by max of previous vector (lane-uniform; slots 0..23 only)
        u32 m0 = bfmax2(q0, q1), m1 = bfmax2(q2, q3), m2 = bfmax2(q4, q5);
        u32 m3 = bfmax2(q6, q7), m4 = bfmax2(q8, q9), m5 = bfmax2(q10, q11);
        m0 = bfmax2(bfmax2(m0, m1), bfmax2(m2, m3));
        m0 = bfmax2(m0, bfmax2(m4, m5));
        float ma, mb;
        bf2f(m0, ma, mb);
        float m = fmaxf(ma, mb);
        vnew = (d0 + d1) * fe * (1.0f / m);
        s += __logf(m);
    } else {
        vnew = (d0 + d1) * fe;
    }
    dst[lane] = f2bf(vnew);  // pad lanes write slots 24..31 (never read)
}

#define STEP(S, D, RN, IDX)                                            \
    do {                                                               \
        step1<RN>(&vh[w][S][0], &vh[w][D][0], lane, E2, fe[IDX], s);   \
        __syncwarp();                                                  \
    } while (0)

#define WIN8(RN0)            \
    STEP(0, 1, RN0, 0);      \
    STEP(1, 0, false, 1);    \
    STEP(0, 1, false, 2);    \
    STEP(1, 0, false, 3);    \
    STEP(0, 1, false, 4);    \
    STEP(1, 0, false, 5);    \
    STEP(0, 1, false, 6);    \
    STEP(1, 0, false, 7)

__global__ __launch_bounds__(64, 14) void crf_kernel(const float* __restrict__ feats,
                                                     const float* __restrict__ trans,
                                                     const void* __restrict__ tags,
                                                     const int* __restrict__ startp,
                                                     float* __restrict__ out) {
    __shared__ __align__(16) u16 vh[2][2][32];  // [warp][buf][state] bf16
    __shared__ float sc_sh;    // backward warp's scale sum
    __shared__ float gold_sh;  // backward warp's gold partial
    const int lane = threadIdx.x & 31;
    const int w = threadIdx.x >> 5;  // 0 = forward, 1 = backward
    const int b = blockIdx.x;
    const int j = (lane < KK) ? lane : (KK - 1);

    const int start = startp[0];  // low word valid for LE int32/int64

    // E2: fwd = row j of exp(trans), paired over i; bwd = column j (E^T)
    u32 E2[12];
    if (w == 0) {
#pragma unroll
        for (int k = 0; k < 12; ++k)
            E2[k] = pkbf(__expf(trans[j * KK + 2 * k]), __expf(trans[j * KK + 2 * k + 1]));
    } else {
#pragma unroll
        for (int k = 0; k < 12; ++k)
            E2[k] = pkbf(__expf(trans[(2 * k) * KK + j]), __expf(trans[(2 * k + 1) * KK + j]));
    }

    float s = 0.0f;
    const float* fb = feats + b * (TT * KK) + j;
    float fn[8], fe[8];

    if (w == 0) {
        // ---------------- forward: alpha, t = 1..256 (32 windows of 8) ----------------
        vh[0][0][lane] = (lane == start) ? f2bf(1.0f) : (u16)0;
#pragma unroll
        for (int r = 0; r < 8; ++r) fn[r] = __ldg(fb + (1 + r) * KK);
        __syncwarp();
        {
#pragma unroll
            for (int r = 0; r < 8; ++r) fe[r] = __expf(fn[r]);
            const float* p = fb + 9 * KK;
#pragma unroll
            for (int r = 0; r < 8; ++r) fn[r] = __ldg(p + r * KK);
            WIN8(false);
        }
#pragma unroll 1
        for (int wi = 1; wi < 32; ++wi) {
#pragma unroll
            for (int r = 0; r < 8; ++r) fe[r] = __expf(fn[r]);
            const float* p = fb + (8 * (wi + 1) + 1) * KK;  // max base 257: in-bounds
#pragma unroll
            for (int r = 0; r < 8; ++r) fn[r] = __ldg(p + r * KK);
            WIN8(true);
        }
        // alpha(256) in vh[0][0]
    } else {
        // -------- backward: s(t)=fe_t*beta(t), t = 511..257, then beta(256) ----------
#pragma unroll
        for (int r = 0; r < 7; ++r) fn[r] = __ldg(fb + (511 - r) * KK);
#pragma unroll
        for (int r = 0; r < 7; ++r) fe[r] = __expf(fn[r]);
        vh[1][0][lane] = (lane < KK) ? f2bf(fe[0]) : (u16)0;  // s(511)
#pragma unroll
        for (int r = 0; r < 8; ++r) fn[r] = __ldg(fb + (504 - r) * KK);
        __syncwarp();
        // prologue: t = 510..505
        STEP(0, 1, false, 1);
        STEP(1, 0, false, 2);
        STEP(0, 1, false, 3);
        STEP(1, 0, false, 4);
        STEP(0, 1, false, 5);
        STEP(1, 0, false, 6);
        // 31 windows of 8: t = 504..257
#pragma unroll 1
        for (int wi = 0; wi < 31; ++wi) {
#pragma unroll
            for (int r = 0; r < 8; ++r) fe[r] = __expf(fn[r]);
            const float* p = fb + (504 - 8 * (wi + 1)) * KK;  // min base 256: in-bounds
#pragma unroll
            for (int r = 0; r < 8; ++r) fn[r] = __ldg(p + r * KK);
            WIN8(true);
        }
        // final fe-free step: beta(256) = E^T s(257)
        step1<false>(&vh[1][0][0], &vh[1][1][0], lane, E2, 1.0f, s);
        __syncwarp();
        if (lane == 0) sc_sh = s;
        // beta(256) in vh[1][1]
    }

    // ---- gold score: warps split the t-range of batch b (exact fp32) ----
    const u32* wds = (const u32*)tags;
    u32 hiw = wds[2 * lane + 1];
    const int is64 = (__ballot_sync(0xffffffffu, hiw != 0u) == 0u);
    float g = 0.0f;
    if (is64) {
        const long long* tg = (const long long*)tags + b * TT;
#pragma unroll
        for (int t = 1 + lane + 32 * w; t < TT; t += 64) {
            int it = (int)tg[t], ip = (int)tg[t - 1];
            g += trans[it * KK + ip] + __ldg(feats + (b * TT + t) * KK + it);
        }
    } else {
        const int* tg = (const int*)tags + b * TT;
#pragma unroll
        for (int t = 1 + lane + 32 * w; t < TT; t += 64) {
            int it = tg[t], ip = tg[t - 1];
            g += trans[it * KK + ip] + __ldg(feats + (b * TT + t) * KK + it);
        }
    }
#pragma unroll
    for (int o = 16; o > 0; o >>= 1) g += __shfl_xor_sync(0xffffffffu, g, o);
    if (w == 1 && lane == 0) gold_sh = g;

    __syncthreads();

    // ---- combine (forward warp): score = log(sum_j alpha_j * beta_j) + sF + sB ----
    if (w == 0) {
        float af, bf2;
        {
            u16 ah = vh[0][0][j];
            u16 bh = vh[1][1][j];
            asm("cvt.f32.bf16 %0, %1;" : "=f"(af) : "h"(ah));
            asm("cvt.f32.bf16 %0, %1;" : "=f"(bf2) : "h"(bh));
        }
        float prod = (lane < KK) ? af * bf2 : 0.0f;
#pragma unroll
        for (int o = 16; o > 0; o >>= 1) prod += __shfl_xor_sync(0xffffffffu, prod, o);
        float fwd = __logf(prod) + s + sc_sh;

        if (lane == 0) {
            double part = (double)fwd - (double)g - (double)gold_sh;
            atomicAdd(&g_sum, part);
            __threadfence();
            u32 old = atomicAdd(&g_ticket, 1u);
            if (old == (u32)(BATCH - 1)) {
                __threadfence();
                out[0] = (float)(g_sum * (1.0 / (double)BATCH));
                g_sum = 0.0;   // self-reset for next graph replay
                g_ticket = 0u;
            }
        }
    }
}

extern "C" void kernel_launch(void* const* d_in, const int* in_sizes, int n_in,
                              void* d_out, int out_size) {
    const float* feats = (const float*)d_in[0];
    const float* trans = (const float*)d_in[1];
    const void* tags = d_in[2];
    const int* startp = (const int*)d_in[3];

    crf_kernel<<<BATCH, 64>>>(feats, trans, tags, startp, (float*)d_out);
}

// round 13
// speedup vs baseline: 1.1838x; 1.0016x over previous
#include <cuda_runtime.h>
#include <cstdint>

#define KK 24
#define TT 512
#define BATCH 2048

// fused final-reduction state (self-resetting -> deterministic across replays)
__device__ double g_sum;
__device__ unsigned int g_ticket;

typedef unsigned int u32;
typedef unsigned short u16;

// ---- bf16x2 helpers ----
static __device__ __forceinline__ u32 bffma2(u32 a, u32 b, u32 c) {
    u32 d;
    asm("fma.rn.bf16x2 %0, %1, %2, %3;" : "=r"(d) : "r"(a), "r"(b), "r"(c));
    return d;
}
static __device__ __forceinline__ u32 bfmul2(u32 a, u32 b) {
    u32 d;
    asm("mul.rn.bf16x2 %0, %1, %2;" : "=r"(d) : "r"(a), "r"(b));
    return d;
}
static __device__ __forceinline__ u32 bfadd2(u32 a, u32 b) {
    u32 d;
    asm("add.rn.bf16x2 %0, %1, %2;" : "=r"(d) : "r"(a), "r"(b));
    return d;
}
static __device__ __forceinline__ u32 bfmax2(u32 a, u32 b) {
    u32 d;
    asm("max.bf16x2 %0, %1, %2;" : "=r"(d) : "r"(a), "r"(b));
    return d;
}
// widen bf16x2 -> 2 floats
static __device__ __forceinline__ void bf2f(u32 v, float& lo, float& hi) {
    u16 l, h;
    asm("mov.b32 {%0, %1}, %2;" : "=h"(l), "=h"(h) : "r"(v));
    asm("cvt.f32.bf16 %0, %1;" : "=f"(lo) : "h"(l));
    asm("cvt.f32.bf16 %0, %1;" : "=f"(hi) : "h"(h));
}
static __device__ __forceinline__ u16 f2bf(float f) {
    u16 h;
    asm("cvt.rn.bf16.f32 %0, %1;" : "=h"(h) : "f"(f));
    return h;
}
// pack (lo, hi) floats -> bf16x2 (PTX: first src -> high half)
static __device__ __forceinline__ u32 pkbf(float lo, float hi) {
    u32 r;
    asm("cvt.rn.bf16x2.f32 %0, %1, %2;" : "=r"(r) : "f"(hi), "f"(lo));
    return r;
}

// one recursion step for ONE batch; v = 24 bf16 in shared.
// E2[k] = bf16x2 (E_{j,2k}, E_{j,2k+1}); q[k] = (v_{2k}, v_{2k+1}).
template <bool RN>
static __device__ __forceinline__ void step1(const u16* __restrict__ src,
                                             u16* __restrict__ dst, int lane,
                                             const u32* __restrict__ E2,
                                             float fe, float& s) {
    const uint4* vp = reinterpret_cast<const uint4*>(src);
    uint4 a = vp[0], b = vp[1], c = vp[2];  // 3 x LDS.128 = 24 bf16 (slots 0..23)
    u32 q0 = a.x, q1 = a.y, q2 = a.z, q3 = a.w;
    u32 q4 = b.x, q5 = b.y, q6 = b.z, q7 = b.w;
    u32 q8 = c.x, q9 = c.y, q10 = c.z, q11 = c.w;

    // 4 parallel chains of depth 3 over state-pairs (bf16 accumulate)
    u32 c0 = bfmul2(E2[0], q0);
    u32 c1 = bfmul2(E2[1], q1);
    u32 c2 = bfmul2(E2[2], q2);
    u32 c3 = bfmul2(E2[3], q3);
    c0 = bffma2(E2[4], q4, c0);
    c1 = bffma2(E2[5], q5, c1);
    c2 = bffma2(E2[6], q6, c2);
    c3 = bffma2(E2[7], q7, c3);
    c0 = bffma2(E2[8], q8, c0);
    c1 = bffma2(E2[9], q9, c1);
    c2 = bffma2(E2[10], q10, c2);
    c3 = bffma2(E2[11], q11, c3);
    u32 ct = bfadd2(bfadd2(c0, c1), bfadd2(c2, c3));
    float d0, d1;
    bf2f(ct, d0, d1);

    float vnew;
    if (RN) {
        // renorm by max of previous vector (lane-uniform; slots 0..23 only)
        u32 m0 = bfmax2(q0, q1), m1 = bfmax2(q2, q3), m2 = bfmax2(q4, q5);
        u32 m3 = bfmax2(q6, q7), m4 = bfmax2(q8, q9), m5 = bfmax2(q10, q11);
        m0 = bfmax2(bfmax2(m0, m1), bfmax2(m2, m3));
        m0 = bfmax2(m0, bfmax2(m4, m5));
        float ma, mb;
        bf2f(m0, ma, mb);
        float m = fmaxf(ma, mb);
        vnew = (d0 + d1) * fe * (1.0f / m);
        s += __logf(m);
    } else {
        vnew = (d0 + d1) * fe;
    }
    dst[lane] = f2bf(vnew);  // pad lanes write slots 24..31 (never read)
}

#define STEP(S, D, RN, IDX)                                            \
    do {                                                               \
        step1<RN>(&vh[w][S][0], &vh[w][D][0], lane, E2, fe[IDX], s);   \
        __syncwarp();                                                  \
    } while (0)

#define WIN8(RN0)            \
    STEP(0, 1, RN0, 0);      \
    STEP(1, 0, false, 1);    \
    STEP(0, 1, false, 2);    \
    STEP(1, 0, false, 3);    \
    STEP(0, 1, false, 4);    \
    STEP(1, 0, false, 5);    \
    STEP(0, 1, false, 6);    \
    STEP(1, 0, false, 7)

__global__ __launch_bounds__(64, 14) void crf_kernel(const float* __restrict__ feats,
                                                     const float* __restrict__ trans,
                                                     const void* __restrict__ tags,
                                                     const int* __restrict__ startp,
                                                     float* __restrict__ out) {
    __shared__ __align__(16) u16 vh[2][2][32];  // [warp][buf][state] bf16
    __shared__ float sc_sh;    // backward warp's scale sum
    __shared__ float gold_sh;  // backward warp's gold partial
    const int lane = threadIdx.x & 31;
    const int w = threadIdx.x >> 5;  // 0 = forward, 1 = backward
    const int b = blockIdx.x;
    const int j = (lane < KK) ? lane : (KK - 1);

    const int start = startp[0];  // low word valid for LE int32/int64

    // E2: fwd = row j of exp(trans), paired over i; bwd = column j (E^T)
    u32 E2[12];
    if (w == 0) {
#pragma unroll
        for (int k = 0; k < 12; ++k)
            E2[k] = pkbf(__expf(trans[j * KK + 2 * k]), __expf(trans[j * KK + 2 * k + 1]));
    } else {
#pragma unroll
        for (int k = 0; k < 12; ++k)
            E2[k] = pkbf(__expf(trans[(2 * k) * KK + j]), __expf(trans[(2 * k + 1) * KK + j]));
    }

    float s = 0.0f;
    const float* fb = feats + b * (TT * KK) + j;
    float fn[8], fe[8];

    if (w == 0) {
        // ---------------- forward: alpha, t = 1..256 (32 windows of 8) ----------------
        vh[0][0][lane] = (lane == start) ? f2bf(1.0f) : (u16)0;
#pragma unroll
        for (int r = 0; r < 8; ++r) fn[r] = __ldg(fb + (1 + r) * KK);
        __syncwarp();
        {
#pragma unroll
            for (int r = 0; r < 8; ++r) fe[r] = __expf(fn[r]);
            const float* p = fb + 9 * KK;
#pragma unroll
            for (int r = 0; r < 8; ++r) fn[r] = __ldg(p + r * KK);
            WIN8(false);
        }
#pragma unroll 1
        for (int wi = 1; wi < 32; ++wi) {
#pragma unroll
            for (int r = 0; r < 8; ++r) fe[r] = __expf(fn[r]);
            const float* p = fb + (8 * (wi + 1) + 1) * KK;  // max base 257: in-bounds
#pragma unroll
            for (int r = 0; r < 8; ++r) fn[r] = __ldg(p + r * KK);
            WIN8(true);
        }
        // alpha(256) in vh[0][0]
    } else {
        // -------- backward: s(t)=fe_t*beta(t), t = 511..257, then beta(256) ----------
#pragma unroll
        for (int r = 0; r < 7; ++r) fn[r] = __ldg(fb + (511 - r) * KK);
#pragma unroll
        for (int r = 0; r < 7; ++r) fe[r] = __expf(fn[r]);
        vh[1][0][lane] = (lane < KK) ? f2bf(fe[0]) : (u16)0;  // s(511)
#pragma unroll
        for (int r = 0; r < 8; ++r) fn[r] = __ldg(fb + (504 - r) * KK);
        __syncwarp();
        // prologue: t = 510..505
        STEP(0, 1, false, 1);
        STEP(1, 0, false, 2);
        STEP(0, 1, false, 3);
        STEP(1, 0, false, 4);
        STEP(0, 1, false, 5);
        STEP(1, 0, false, 6);
        // 31 windows of 8: t = 504..257
#pragma unroll 1
        for (int wi = 0; wi < 31; ++wi) {
#pragma unroll
            for (int r = 0; r < 8; ++r) fe[r] = __expf(fn[r]);
            const float* p = fb + (504 - 8 * (wi + 1)) * KK;  // min base 256: in-bounds
#pragma unroll
            for (int r = 0; r < 8; ++r) fn[r] = __ldg(p + r * KK);
            WIN8(true);
        }
        // final fe-free step: beta(256) = E^T s(257)
        step1<false>(&vh[1][0][0], &vh[1][1][0], lane, E2, 1.0f, s);
        __syncwarp();
        if (lane == 0) sc_sh = s;
        // beta(256) in vh[1][1]
    }

    // ---- gold score: warps split the t-range of batch b (exact fp32) ----
    const u32* wds = (const u32*)tags;
    u32 hiw = wds[2 * lane + 1];
    const int is64 = (__ballot_sync(0xffffffffu, hiw != 0u) == 0u);
    float g = 0.0f;
    if (is64) {
        const long long* tg = (const long long*)tags + b * TT;
#pragma unroll
        for (int t = 1 + lane + 32 * w; t < TT; t += 64) {
            int it = (int)tg[t], ip = (int)tg[t - 1];
            g += trans[it * KK + ip] + __ldg(feats + (b * TT + t) * KK + it);
        }
    } else {
        const int* tg = (const int*)tags + b * TT;
#pragma unroll
        for (int t = 1 + lane + 32 * w; t < TT; t += 64) {
            int it = tg[t], ip = tg[t - 1];
            g += trans[it * KK + ip] + __ldg(feats + (b * TT + t) * KK + it);
        }
    }
#pragma unroll
    for (int o = 16; o > 0; o >>= 1) g += __shfl_xor_sync(0xffffffffu, g, o);
    if (w == 1 && lane == 0) gold_sh = g;

    __syncthreads();

    // ---- combine (forward warp): score = log(sum_j alpha_j * beta_j) + sF + sB ----
    if (w == 0) {
        float af, bf2;
        {
            u16 ah = vh[0][0][j];
            u16 bh = vh[1][1][j];
            asm("cvt.f32.bf16 %0, %1;" : "=f"(af) : "h"(ah));
            asm("cvt.f32.bf16 %0, %1;" : "=f"(bf2) : "h"(bh));
        }
        float prod = (lane < KK) ? af * bf2 : 0.0f;
#pragma unroll
        for (int o = 16; o > 0; o >>= 1) prod += __shfl_xor_sync(0xffffffffu, prod, o);
        float fwd = __logf(prod) + s + sc_sh;

        if (lane == 0) {
            double part = (double)fwd - (double)g - (double)gold_sh;
            atomicAdd(&g_sum, part);
            __threadfence();
            u32 old = atomicAdd(&g_ticket, 1u);
            if (old == (u32)(BATCH - 1)) {
                __threadfence();
                out[0] = (float)(g_sum * (1.0 / (double)BATCH));
                g_sum = 0.0;   // self-reset for next graph replay
                g_ticket = 0u;
            }
        }
    }
}

extern "C" void kernel_launch(void* const* d_in, const int* in_sizes, int n_in,
                              void* d_out, int out_size) {
    const float* feats = (const float*)d_in[0];
    const float* trans = (const float*)d_in[1];
    const void* tags = d_in[2];
    const int* startp = (const int*)d_in[3];

    crf_kernel<<<BATCH, 64>>>(feats, trans, tags, startp, (float*)d_out);
}

// round 14
// speedup vs baseline: 1.1844x; 1.0005x over previous
#include <cuda_runtime.h>
#include <cstdint>

#define KK 24
#define TT 512
#define BATCH 2048

// fused final-reduction state (self-resetting -> deterministic across replays)
__device__ double g_sum;
__device__ unsigned int g_ticket;

typedef unsigned int u32;
typedef unsigned short u16;

// ---- bf16x2 helpers ----
static __device__ __forceinline__ u32 bffma2(u32 a, u32 b, u32 c) {
    u32 d;
    asm("fma.rn.bf16x2 %0, %1, %2, %3;" : "=r"(d) : "r"(a), "r"(b), "r"(c));
    return d;
}
static __device__ __forceinline__ u32 bfmul2(u32 a, u32 b) {
    u32 d;
    asm("mul.rn.bf16x2 %0, %1, %2;" : "=r"(d) : "r"(a), "r"(b));
    return d;
}
static __device__ __forceinline__ u32 bfadd2(u32 a, u32 b) {
    u32 d;
    asm("add.rn.bf16x2 %0, %1, %2;" : "=r"(d) : "r"(a), "r"(b));
    return d;
}
static __device__ __forceinline__ u32 bfmax2(u32 a, u32 b) {
    u32 d;
    asm("max.bf16x2 %0, %1, %2;" : "=r"(d) : "r"(a), "r"(b));
    return d;
}
static __device__ __forceinline__ void bf2f(u32 v, float& lo, float& hi) {
    u16 l, h;
    asm("mov.b32 {%0, %1}, %2;" : "=h"(l), "=h"(h) : "r"(v));
    asm("cvt.f32.bf16 %0, %1;" : "=f"(lo) : "h"(l));
    asm("cvt.f32.bf16 %0, %1;" : "=f"(hi) : "h"(h));
}
static __device__ __forceinline__ u16 f2bf(float f) {
    u16 h;
    asm("cvt.rn.bf16.f32 %0, %1;" : "=h"(h) : "f"(f));
    return h;
}
// pack (lo, hi) floats -> bf16x2 (PTX: first src -> high half)
static __device__ __forceinline__ u32 pkbf(float lo, float hi) {
    u32 r;
    asm("cvt.rn.bf16x2.f32 %0, %1, %2;" : "=r"(r) : "f"(hi), "f"(lo));
    return r;
}
// swap 16-bit halves
static __device__ __forceinline__ u32 swap16(u32 v) {
    u32 r;
    asm("prmt.b32 %0, %1, %1, 0x1032;" : "=r"(r) : "r"(v));
    return r;
}

// one recursion step, ONE batch, all-bf16 datapath.
// E2[k] = bf16x2 (E_{j,2k}, E_{j,2k+1}); fe2 = duplicated bf16x2 exp(feat_j).
template <bool RN>
static __device__ __forceinline__ void step1(const u16* __restrict__ src,
                                             u16* __restrict__ dst, int lane,
                                             const u32* __restrict__ E2,
                                             u32 fe2, float& s) {
    const uint4* vp = reinterpret_cast<const uint4*>(src);
    uint4 a = vp[0], b = vp[1], c = vp[2];  // 3 x LDS.128 = 24 bf16
    u32 q0 = a.x, q1 = a.y, q2 = a.z, q3 = a.w;
    u32 q4 = b.x, q5 = b.y, q6 = b.z, q7 = b.w;
    u32 q8 = c.x, q9 = c.y, q10 = c.z, q11 = c.w;

    // 4 parallel chains of depth 3 over state-pairs
    u32 c0 = bfmul2(E2[0], q0);
    u32 c1 = bfmul2(E2[1], q1);
    u32 c2 = bfmul2(E2[2], q2);
    u32 c3 = bfmul2(E2[3], q3);
    c0 = bffma2(E2[4], q4, c0);
    c1 = bffma2(E2[5], q5, c1);
    c2 = bffma2(E2[6], q6, c2);
    c3 = bffma2(E2[7], q7, c3);
    c0 = bffma2(E2[8], q8, c0);
    c1 = bffma2(E2[9], q9, c1);
    c2 = bffma2(E2[10], q10, c2);
    c3 = bffma2(E2[11], q11, c3);
    u32 ct = bfadd2(bfadd2(c0, c1), bfadd2(c2, c3));
    // horizontal: both halves become (lo+hi), then scale by fe (packed dup)
    u32 tot = bfadd2(ct, swap16(ct));
    u32 vq = bfmul2(tot, fe2);

    if (RN) {
        // renorm by max of previous vector (lane-uniform)
        u32 m0 = bfmax2(q0, q1), m1 = bfmax2(q2, q3), m2 = bfmax2(q4, q5);
        u32 m3 = bfmax2(q6, q7), m4 = bfmax2(q8, q9), m5 = bfmax2(q10, q11);
        m0 = bfmax2(bfmax2(m0, m1), bfmax2(m2, m3));
        m0 = bfmax2(m0, bfmax2(m4, m5));
        float ma, mb;
        bf2f(m0, ma, mb);
        float m = fmaxf(ma, mb);
        float inv = 1.0f / m;
        vq = bfmul2(vq, pkbf(inv, inv));
        s += __logf(m);
    }
    dst[lane] = (u16)vq;  // low half; pad lanes write slots 24..31 (never read)
}

#define STEP(S, D, RN, IDX)                                             \
    do {                                                                \
        step1<RN>(&vh[w][S][0], &vh[w][D][0], lane, E2, fe2[IDX], s);   \
        __syncwarp();                                                   \
    } while (0)

#define WIN8(RN0)            \
    STEP(0, 1, RN0, 0);      \
    STEP(1, 0, false, 1);    \
    STEP(0, 1, false, 2);    \
    STEP(1, 0, false, 3);    \
    STEP(0, 1, false, 4);    \
    STEP(1, 0, false, 5);    \
    STEP(0, 1, false, 6);    \
    STEP(1, 0, false, 7)

__global__ __launch_bounds__(64, 14) void crf_kernel(const float* __restrict__ feats,
                                                     const float* __restrict__ trans,
                                                     const void* __restrict__ tags,
                                                     const int* __restrict__ startp,
                                                     float* __restrict__ out) {
    __shared__ __align__(16) u16 vh[2][2][32];  // [warp][buf][state] bf16
    __shared__ float sc_sh;    // backward warp's scale sum
    __shared__ float gold_sh;  // backward warp's gold partial
    const int lane = threadIdx.x & 31;
    const int w = threadIdx.x >> 5;  // 0 = forward, 1 = backward
    const int b = blockIdx.x;
    const int j = (lane < KK) ? lane : (KK - 1);

    const int start = startp[0];  // low word valid for LE int32/int64

    // E2: fwd = row j of exp(trans), paired over i; bwd = column j (E^T)
    u32 E2[12];
    if (w == 0) {
#pragma unroll
        for (int k = 0; k < 12; ++k)
            E2[k] = pkbf(__expf(trans[j * KK + 2 * k]), __expf(trans[j * KK + 2 * k + 1]));
    } else {
#pragma unroll
        for (int k = 0; k < 12; ++k)
            E2[k] = pkbf(__expf(trans[(2 * k) * KK + j]), __expf(trans[(2 * k + 1) * KK + j]));
    }

    float s = 0.0f;
    const float* fb = feats + b * (TT * KK) + j;
    float fn[8];
    u32 fe2[8];

    if (w == 0) {
        // ---------------- forward: alpha, t = 1..256 (32 windows of 8) ----------------
        vh[0][0][lane] = (lane == start) ? f2bf(1.0f) : (u16)0;
#pragma unroll
        for (int r = 0; r < 8; ++r) fn[r] = __ldg(fb + (1 + r) * KK);
        __syncwarp();
        {
#pragma unroll
            for (int r = 0; r < 8; ++r) {
                float e = __expf(fn[r]);
                fe2[r] = pkbf(e, e);
            }
            const float* p = fb + 9 * KK;
#pragma unroll
            for (int r = 0; r < 8; ++r) fn[r] = __ldg(p + r * KK);
            WIN8(false);
        }
#pragma unroll 1
        for (int wi = 1; wi < 32; ++wi) {
#pragma unroll
            for (int r = 0; r < 8; ++r) {
                float e = __expf(fn[r]);
                fe2[r] = pkbf(e, e);
            }
            const float* p = fb + (8 * (wi + 1) + 1) * KK;  // max base 257: in-bounds
#pragma unroll
            for (int r = 0; r < 8; ++r) fn[r] = __ldg(p + r * KK);
            WIN8(true);
        }
        // alpha(256) in vh[0][0]
    } else {
        // -------- backward: s(t)=fe_t*beta(t), t = 511..257, then beta(256) ----------
#pragma unroll
        for (int r = 0; r < 7; ++r) fn[r] = __ldg(fb + (511 - r) * KK);
        float e0 = __expf(fn[0]);
#pragma unroll
        for (int r = 0; r < 7; ++r) {
            float e = (r == 0) ? e0 : __expf(fn[r]);
            fe2[r] = pkbf(e, e);
        }
        vh[1][0][lane] = (lane < KK) ? f2bf(e0) : (u16)0;  // s(511)
#pragma unroll
        for (int r = 0; r < 8; ++r) fn[r] = __ldg(fb + (504 - r) * KK);
        __syncwarp();
        // prologue: t = 510..505
        STEP(0, 1, false, 1);
        STEP(1, 0, false, 2);
        STEP(0, 1, false, 3);
        STEP(1, 0, false, 4);
        STEP(0, 1, false, 5);
        STEP(1, 0, false, 6);
        // 31 windows of 8: t = 504..257
#pragma unroll 1
        for (int wi = 0; wi < 31; ++wi) {
#pragma unroll
            for (int r = 0; r < 8; ++r) {
                float e = __expf(fn[r]);
                fe2[r] = pkbf(e, e);
            }
            const float* p = fb + (504 - 8 * (wi + 1)) * KK;  // min base 256: in-bounds
#pragma unroll
            for (int r = 0; r < 8; ++r) fn[r] = __ldg(p + r * KK);
            WIN8(true);
        }
        // final fe-free step: beta(256) = E^T s(257)
        step1<false>(&vh[1][0][0], &vh[1][1][0], lane, E2, 0x3F803F80u /* (1,1) */, s);
        __syncwarp();
        if (lane == 0) sc_sh = s;
        // beta(256) in vh[1][1]
    }

    // ---- gold score: warps split the t-range of batch b (exact fp32) ----
    const u32* wds = (const u32*)tags;
    u32 hiw = wds[2 * lane + 1];
    const int is64 = (__ballot_sync(0xffffffffu, hiw != 0u) == 0u);
    float g = 0.0f;
    if (is64) {
        const long long* tg = (const long long*)tags + b * TT;
#pragma unroll
        for (int t = 1 + lane + 32 * w; t < TT; t += 64) {
            int it = (int)tg[t], ip = (int)tg[t - 1];
            g += trans[it * KK + ip] + __ldg(feats + (b * TT + t) * KK + it);
        }
    } else {
        const int* tg = (const int*)tags + b * TT;
#pragma unroll
        for (int t = 1 + lane + 32 * w; t < TT; t += 64) {
            int it = tg[t], ip = tg[t - 1];
            g += trans[it * KK + ip] + __ldg(feats + (b * TT + t) * KK + it);
        }
    }
#pragma unroll
    for (int o = 16; o > 0; o >>= 1) g += __shfl_xor_sync(0xffffffffu, g, o);
    if (w == 1 && lane == 0) gold_sh = g;

    __syncthreads();

    // ---- combine (forward warp): score = log(sum_j alpha_j * beta_j) + sF + sB ----
    if (w == 0) {
        float af, bf;
        {
            u16 ah = vh[0][0][j];
            u16 bh = vh[1][1][j];
            asm("cvt.f32.bf16 %0, %1;" : "=f"(af) : "h"(ah));
            asm("cvt.f32.bf16 %0, %1;" : "=f"(bf) : "h"(bh));
        }
        float prod = (lane < KK) ? af * bf : 0.0f;
#pragma unroll
        for (int o = 16; o > 0; o >>= 1) prod += __shfl_xor_sync(0xffffffffu, prod, o);
        float fwd = __logf(prod) + s + sc_sh;

        if (lane == 0) {
            double part = (double)fwd - (double)g - (double)gold_sh;
            atomicAdd(&g_sum, part);
            __threadfence();
            u32 old = atomicAdd(&g_ticket, 1u);
            if (old == (u32)(BATCH - 1)) {
                __threadfence();
                out[0] = (float)(g_sum * (1.0 / (double)BATCH));
                g_sum = 0.0;   // self-reset for next graph replay
                g_ticket = 0u;
            }
        }
    }
}

extern "C" void kernel_launch(void* const* d_in, const int* in_sizes, int n_in,
                              void* d_out, int out_size) {
    const float* feats = (const float*)d_in[0];
    const float* trans = (const float*)d_in[1];
    const void* tags = d_in[2];
    const int* startp = (const int*)d_in[3];

    crf_kernel<<<BATCH, 64>>>(feats, trans, tags, startp, (float*)d_out);
}

// round 15
// speedup vs baseline: 1.1862x; 1.0016x over previous
#include <cuda_runtime.h>
#include <cstdint>

#define KK 24
#define TT 512
#define BATCH 2048

// fused final-reduction state (self-resetting -> deterministic across replays)
__device__ double g_sum;
__device__ unsigned int g_ticket;

typedef unsigned int u32;
typedef unsigned short u16;

// ---- bf16x2 helpers ----
static __device__ __forceinline__ u32 bffma2(u32 a, u32 b, u32 c) {
    u32 d;
    asm("fma.rn.bf16x2 %0, %1, %2, %3;" : "=r"(d) : "r"(a), "r"(b), "r"(c));
    return d;
}
static __device__ __forceinline__ u32 bfmul2(u32 a, u32 b) {
    u32 d;
    asm("mul.rn.bf16x2 %0, %1, %2;" : "=r"(d) : "r"(a), "r"(b));
    return d;
}
static __device__ __forceinline__ u32 bfadd2(u32 a, u32 b) {
    u32 d;
    asm("add.rn.bf16x2 %0, %1, %2;" : "=r"(d) : "r"(a), "r"(b));
    return d;
}
static __device__ __forceinline__ u32 bfmax2(u32 a, u32 b) {
    u32 d;
    asm("max.bf16x2 %0, %1, %2;" : "=r"(d) : "r"(a), "r"(b));
    return d;
}
static __device__ __forceinline__ void bf2f(u32 v, float& lo, float& hi) {
    u16 l, h;
    asm("mov.b32 {%0, %1}, %2;" : "=h"(l), "=h"(h) : "r"(v));
    asm("cvt.f32.bf16 %0, %1;" : "=f"(lo) : "h"(l));
    asm("cvt.f32.bf16 %0, %1;" : "=f"(hi) : "h"(h));
}
static __device__ __forceinline__ u16 f2bf(float f) {
    u16 h;
    asm("cvt.rn.bf16.f32 %0, %1;" : "=h"(h) : "f"(f));
    return h;
}
// pack (lo, hi) floats -> bf16x2 (PTX: first src -> high half)
static __device__ __forceinline__ u32 pkbf(float lo, float hi) {
    u32 r;
    asm("cvt.rn.bf16x2.f32 %0, %1, %2;" : "=r"(r) : "f"(hi), "f"(lo));
    return r;
}
static __device__ __forceinline__ u32 swap16(u32 v) {
    u32 r;
    asm("prmt.b32 %0, %1, %1, 0x1032;" : "=r"(r) : "r"(v));
    return r;
}
// ordered shared ops (32-bit shared-window addresses); "memory" clobber pins
// program order; warp-wide LSU executes same-warp smem ops in issue order.
static __device__ __forceinline__ uint4 lds128(u32 addr) {
    uint4 v;
    asm volatile("ld.shared.v4.b32 {%0,%1,%2,%3}, [%4];"
                 : "=r"(v.x), "=r"(v.y), "=r"(v.z), "=r"(v.w) : "r"(addr) : "memory");
    return v;
}
static __device__ __forceinline__ void sts16(u32 addr, u32 val) {
    asm volatile("st.shared.u16 [%0], %1;" :: "r"(addr), "r"(val) : "memory");
}
static __device__ __forceinline__ u32 smem_u32(const void* p) {
    u32 a;
    asm("{ .reg .u64 t; cvta.to.shared.u64 t, %1; cvt.u32.u64 %0, t; }" : "=r"(a) : "l"(p));
    return a;
}

// one recursion step, ONE batch, all-bf16 datapath, no warp barrier.
template <bool RN>
static __device__ __forceinline__ void step1(u32 src, u32 dst,
                                             const u32* __restrict__ E2,
                                             u32 fe2, float& s) {
    uint4 A = lds128(src), B = lds128(src + 16), C = lds128(src + 32);
    u32 q0 = A.x, q1 = A.y, q2 = A.z, q3 = A.w;
    u32 q4 = B.x, q5 = B.y, q6 = B.z, q7 = B.w;
    u32 q8 = C.x, q9 = C.y, q10 = C.z, q11 = C.w;

    u32 c0 = bfmul2(E2[0], q0);
    u32 c1 = bfmul2(E2[1], q1);
    u32 c2 = bfmul2(E2[2], q2);
    u32 c3 = bfmul2(E2[3], q3);
    c0 = bffma2(E2[4], q4, c0);
    c1 = bffma2(E2[5], q5, c1);
    c2 = bffma2(E2[6], q6, c2);
    c3 = bffma2(E2[7], q7, c3);
    c0 = bffma2(E2[8], q8, c0);
    c1 = bffma2(E2[9], q9, c1);
    c2 = bffma2(E2[10], q10, c2);
    c3 = bffma2(E2[11], q11, c3);
    u32 ct = bfadd2(bfadd2(c0, c1), bfadd2(c2, c3));
    u32 tot = bfadd2(ct, swap16(ct));  // both halves = lo+hi
    u32 vq = bfmul2(tot, fe2);

    if (RN) {
        u32 m0 = bfmax2(q0, q1), m1 = bfmax2(q2, q3), m2 = bfmax2(q4, q5);
        u32 m3 = bfmax2(q6, q7), m4 = bfmax2(q8, q9), m5 = bfmax2(q10, q11);
        m0 = bfmax2(bfmax2(m0, m1), bfmax2(m2, m3));
        m0 = bfmax2(m0, bfmax2(m4, m5));
        float ma, mb;
        bf2f(m0, ma, mb);
        float m = fmaxf(ma, mb);
        float inv = 1.0f / m;
        vq = bfmul2(vq, pkbf(inv, inv));
        s += __logf(m);
    }
    sts16(dst, vq);
}

// src buffer address / dst lane address alternate between the two buffers
#define STEP(SA, DA, RN, IDX) step1<RN>(SA, DA, E2, fe2[IDX], s)

#define WIN8(RN0)                 \
    STEP(a0, d1, RN0, 0);         \
    STEP(a1, d0, false, 1);       \
    STEP(a0, d1, false, 2);       \
    STEP(a1, d0, false, 3);       \
    STEP(a0, d1, false, 4);       \
    STEP(a1, d0, false, 5);       \
    STEP(a0, d1, false, 6);       \
    STEP(a1, d0, false, 7)

__global__ __launch_bounds__(64, 14) void crf_kernel(const float* __restrict__ feats,
                                                     const float* __restrict__ trans,
                                                     const void* __restrict__ tags,
                                                     const int* __restrict__ startp,
                                                     float* __restrict__ out) {
    __shared__ __align__(16) u16 vh[2][2][32];  // [warp][buf][state] bf16
    __shared__ float sc_sh;    // backward warp's scale sum
    __shared__ float gold_sh;  // backward warp's gold partial
    const int lane = threadIdx.x & 31;
    const int w = threadIdx.x >> 5;  // 0 = forward, 1 = backward
    const int b = blockIdx.x;
    const int j = (lane < KK) ? lane : (KK - 1);

    const int start = startp[0];  // low word valid for LE int32/int64

    // 32-bit shared addresses for this warp's two buffers
    const u32 sb = smem_u32(&vh[0][0][0]);
    const u32 a0 = sb + (w * 2 + 0) * 64;       // buffer 0 base (uniform)
    const u32 a1 = sb + (w * 2 + 1) * 64;       // buffer 1 base (uniform)
    const u32 d0 = a0 + lane * 2;               // per-lane store slots
    const u32 d1 = a1 + lane * 2;

    // E2: fwd = row j of exp(trans), paired over i; bwd = column j (E^T)
    u32 E2[12];
    if (w == 0) {
#pragma unroll
        for (int k = 0; k < 12; ++k)
            E2[k] = pkbf(__expf(trans[j * KK + 2 * k]), __expf(trans[j * KK + 2 * k + 1]));
    } else {
#pragma unroll
        for (int k = 0; k < 12; ++k)
            E2[k] = pkbf(__expf(trans[(2 * k) * KK + j]), __expf(trans[(2 * k + 1) * KK + j]));
    }

    float s = 0.0f;
    const float* fb = feats + b * (TT * KK) + j;
    float fn[8];
    u32 fe2[8];

    if (w == 0) {
        // ---------------- forward: alpha, t = 1..256 (32 windows of 8) ----------------
        sts16(d0, (lane == start) ? 0x3F80u : 0u);  // bf16 1.0 / 0.0
#pragma unroll
        for (int r = 0; r < 8; ++r) fn[r] = __ldg(fb + (1 + r) * KK);
        __syncwarp();
        {
#pragma unroll
            for (int r = 0; r < 8; ++r) {
                float e = __expf(fn[r]);
                fe2[r] = pkbf(e, e);
            }
            const float* p = fb + 9 * KK;
#pragma unroll
            for (int r = 0; r < 8; ++r) fn[r] = __ldg(p + r * KK);
            WIN8(false);
        }
#pragma unroll 1
        for (int wi = 1; wi < 32; ++wi) {
#pragma unroll
            for (int r = 0; r < 8; ++r) {
                float e = __expf(fn[r]);
                fe2[r] = pkbf(e, e);
            }
            const float* p = fb + (8 * (wi + 1) + 1) * KK;  // max base 257: in-bounds
#pragma unroll
            for (int r = 0; r < 8; ++r) fn[r] = __ldg(p + r * KK);
            WIN8(true);
        }
        // alpha(256) in buffer 0
    } else {
        // -------- backward: s(t)=fe_t*beta(t), t = 511..257, then beta(256) ----------
#pragma unroll
        for (int r = 0; r < 7; ++r) fn[r] = __ldg(fb + (511 - r) * KK);
        float e0 = __expf(fn[0]);
#pragma unroll
        for (int r = 0; r < 7; ++r) {
            float e = (r == 0) ? e0 : __expf(fn[r]);
            fe2[r] = pkbf(e, e);
        }
        sts16(d0, (lane < KK) ? (u32)f2bf(e0) : 0u);  // s(511)
#pragma unroll
        for (int r = 0; r < 8; ++r) fn[r] = __ldg(fb + (504 - r) * KK);
        __syncwarp();
        // prologue: t = 510..505
        STEP(a0, d1, false, 1);
        STEP(a1, d0, false, 2);
        STEP(a0, d1, false, 3);
        STEP(a1, d0, false, 4);
        STEP(a0, d1, false, 5);
        STEP(a1, d0, false, 6);
        // 31 windows of 8: t = 504..257
#pragma unroll 1
        for (int wi = 0; wi < 31; ++wi) {
#pragma unroll
            for (int r = 0; r < 8; ++r) {
                float e = __expf(fn[r]);
                fe2[r] = pkbf(e, e);
            }
            const float* p = fb + (504 - 8 * (wi + 1)) * KK;  // min base 256: in-bounds
#pragma unroll
            for (int r = 0; r < 8; ++r) fn[r] = __ldg(p + r * KK);
            WIN8(true);
        }
        // final fe-free step: beta(256) = E^T s(257); buffer0 -> buffer1
        step1<false>(a0, d1, E2, 0x3F803F80u /* (1,1) */, s);
        __syncwarp();
        if (lane == 0) sc_sh = s;
        // beta(256) in buffer 1 of warp 1
    }

    // ---- gold score: warps split the t-range of batch b (exact fp32) ----
    const u32* wds = (const u32*)tags;
    u32 hiw = wds[2 * lane + 1];
    const int is64 = (__ballot_sync(0xffffffffu, hiw != 0u) == 0u);
    float g = 0.0f;
    if (is64) {
        const long long* tg = (const long long*)tags + b * TT;
#pragma unroll
        for (int t = 1 + lane + 32 * w; t < TT; t += 64) {
            int it = (int)tg[t], ip = (int)tg[t - 1];
            g += trans[it * KK + ip] + __ldg(feats + (b * TT + t) * KK + it);
        }
    } else {
        const int* tg = (const int*)tags + b * TT;
#pragma unroll
        for (int t = 1 + lane + 32 * w; t < TT; t += 64) {
            int it = tg[t], ip = tg[t - 1];
            g += trans[it * KK + ip] + __ldg(feats + (b * TT + t) * KK + it);
        }
    }
#pragma unroll
    for (int o = 16; o > 0; o >>= 1) g += __shfl_xor_sync(0xffffffffu, g, o);
    if (w == 1 && lane == 0) gold_sh = g;

    __syncthreads();

    // ---- combine (forward warp): score = log(sum_j alpha_j * beta_j) + sF + sB ----
    if (w == 0) {
        float af, bf;
        {
            u16 ah = vh[0][0][j];  // alpha(256): warp0 buffer0
            u16 bh = vh[1][1][j];  // beta(256):  warp1 buffer1
            asm("cvt.f32.bf16 %0, %1;" : "=f"(af) : "h"(ah));
            asm("cvt.f32.bf16 %0, %1;" : "=f"(bf) : "h"(bh));
        }
        float prod = (lane < KK) ? af * bf : 0.0f;
#pragma unroll
        for (int o = 16; o > 0; o >>= 1) prod += __shfl_xor_sync(0xffffffffu, prod, o);
        float fwd = __logf(prod) + s + sc_sh;

        if (lane == 0) {
            double part = (double)fwd - (double)g - (double)gold_sh;
            atomicAdd(&g_sum, part);
            __threadfence();
            u32 old = atomicAdd(&g_ticket, 1u);
            if (old == (u32)(BATCH - 1)) {
                __threadfence();
                out[0] = (float)(g_sum * (1.0 / (double)BATCH));
                g_sum = 0.0;   // self-reset for next graph replay
                g_ticket = 0u;
            }
        }
    }
}

extern "C" void kernel_launch(void* const* d_in, const int* in_sizes, int n_in,
                              void* d_out, int out_size) {
    const float* feats = (const float*)d_in[0];
    const float* trans = (const float*)d_in[1];
    const void* tags = d_in[2];
    const int* startp = (const int*)d_in[3];

    crf_kernel<<<BATCH, 64>>>(feats, trans, tags, startp, (float*)d_out);
}